// round 1
// baseline (speedup 1.0000x reference)
#include <cuda_runtime.h>

// out[n,i] = sum_{m<K} W[i, m*D+i] * h_r[n, m*D+i] + b[i]
// N=8192, D=1024, K=8. Pure HBM streaming: 256MB read + 32MB write.

constexpr int D = 1024;
constexpr int K = 8;
constexpr int KD = K * D;           // 8192
constexpr int THREADS = 256;        // each thread: 4 consecutive output cols
constexpr int ROWS_PER_BLOCK = 8;

__global__ __launch_bounds__(THREADS, 8)
void imputation_kernel(const float* __restrict__ h_r,
                       const float* __restrict__ W,
                       const float* __restrict__ b,
                       float* __restrict__ out,
                       int n_rows) {
    // w_diag[m][i] = W[i, m*D + i]; 8192 floats = 32 KB
    __shared__ float wd[K][D];
    __shared__ float bs[D];

    const int t = threadIdx.x;

    // Gather the diagonal of W into smem (scattered, but only 32 KB total
    // working set chip-wide -> L2 resident after the first wave).
    #pragma unroll
    for (int idx = t; idx < KD; idx += THREADS) {
        const int m = idx >> 10;        // idx / D
        const int i = idx & (D - 1);    // idx % D
        wd[m][i] = W[(size_t)i * KD + m * D + i];
    }
    #pragma unroll
    for (int i = t; i < D; i += THREADS) {
        bs[i] = b[i];
    }
    __syncthreads();

    const int row0 = blockIdx.x * ROWS_PER_BLOCK;

    // Preload this thread's weight columns from smem into registers
    // (reused across all 8 rows of the block).
    const int c4 = t * 4;
    float4 wreg[K];
    #pragma unroll
    for (int m = 0; m < K; m++) {
        wreg[m] = *reinterpret_cast<const float4*>(&wd[m][c4]);
    }
    const float4 breg = *reinterpret_cast<const float4*>(&bs[c4]);

    #pragma unroll 2
    for (int r = 0; r < ROWS_PER_BLOCK; r++) {
        const int n = row0 + r;
        if (n >= n_rows) return;
        const float4* __restrict__ hp =
            reinterpret_cast<const float4*>(h_r + (size_t)n * KD);

        float a0 = breg.x, a1 = breg.y, a2 = breg.z, a3 = breg.w;

        // 8 independent float4 loads -> MLP=8 per thread per row.
        float4 h[K];
        #pragma unroll
        for (int m = 0; m < K; m++) {
            h[m] = hp[m * (D / 4) + t];
        }
        #pragma unroll
        for (int m = 0; m < K; m++) {
            a0 = fmaf(h[m].x, wreg[m].x, a0);
            a1 = fmaf(h[m].y, wreg[m].y, a1);
            a2 = fmaf(h[m].z, wreg[m].z, a2);
            a3 = fmaf(h[m].w, wreg[m].w, a3);
        }

        float4 o = make_float4(a0, a1, a2, a3);
        *reinterpret_cast<float4*>(out + (size_t)n * D + c4) = o;
    }
}

extern "C" void kernel_launch(void* const* d_in, const int* in_sizes, int n_in,
                              void* d_out, int out_size) {
    const float* h_r = (const float*)d_in[0];
    const float* W   = (const float*)d_in[1];
    const float* b   = (const float*)d_in[2];
    float* out       = (float*)d_out;

    const int n_rows = in_sizes[0] / KD;   // 8192
    const int blocks = (n_rows + ROWS_PER_BLOCK - 1) / ROWS_PER_BLOCK;

    imputation_kernel<<<blocks, THREADS>>>(h_r, W, b, out, n_rows);
}

// round 2
// speedup vs baseline: 2.9279x; 2.9279x over previous
#include <cuda_runtime.h>

// out[n,i] = sum_{m<K} W[i, m*D+i] * h_r[n, m*D+i] + b[i]
// N=8192, D=1024, K=8. HBM streaming: 256MB read + 32MB write -> ~36us floor.

constexpr int D = 1024;
constexpr int K = 8;
constexpr int KD = K * D;           // 8192
constexpr int THREADS = 256;        // thread t owns output cols [4t, 4t+4)
constexpr int ROWS_PER_BLOCK = 8;

// Gathered diagonal of W: g_wd[m*D + i] = W[i, m*D + i]
__device__ float g_wd[KD];

__global__ void gather_wdiag_kernel(const float* __restrict__ W) {
    const int idx = blockIdx.x * blockDim.x + threadIdx.x;
    if (idx < KD) {
        const int m = idx >> 10;
        const int i = idx & (D - 1);
        g_wd[idx] = W[(size_t)i * KD + m * D + i];
    }
}

__global__ __launch_bounds__(THREADS, 4)
void imputation_kernel(const float* __restrict__ h_r,
                       const float* __restrict__ b,
                       float* __restrict__ out,
                       int n_rows) {
    __shared__ float4 wd4[K][THREADS];
    __shared__ float4 bs4[THREADS];

    const int t = threadIdx.x;

    // Coalesced load of the pre-gathered diagonal (8 KB working set, L2-hit).
    const float4* gw4 = reinterpret_cast<const float4*>(g_wd);
    #pragma unroll
    for (int m = 0; m < K; m++) {
        wd4[m][t] = gw4[m * THREADS + t];
    }
    bs4[t] = reinterpret_cast<const float4*>(b)[t];
    __syncthreads();

    const int row0 = blockIdx.x * ROWS_PER_BLOCK;
    const int row_end = min(row0 + ROWS_PER_BLOCK, n_rows);

    for (int n = row0; n < row_end; n++) {
        const float4* __restrict__ hp =
            reinterpret_cast<const float4*>(h_r + (size_t)n * KD);

        // 8 independent streaming loads in flight (MLP=8 per thread).
        float4 h[K];
        #pragma unroll
        for (int m = 0; m < K; m++) {
            h[m] = __ldcs(&hp[m * (D / 4) + t]);
        }

        float4 acc = bs4[t];
        #pragma unroll
        for (int m = 0; m < K; m++) {
            const float4 w = wd4[m][t];   // LDS.128, conflict-free
            acc.x = fmaf(h[m].x, w.x, acc.x);
            acc.y = fmaf(h[m].y, w.y, acc.y);
            acc.z = fmaf(h[m].z, w.z, acc.z);
            acc.w = fmaf(h[m].w, w.w, acc.w);
        }

        __stcs(reinterpret_cast<float4*>(out + (size_t)n * D) + t, acc);
    }
}

extern "C" void kernel_launch(void* const* d_in, const int* in_sizes, int n_in,
                              void* d_out, int out_size) {
    const float* h_r = (const float*)d_in[0];
    const float* W   = (const float*)d_in[1];
    const float* b   = (const float*)d_in[2];
    float* out       = (float*)d_out;

    const int n_rows = in_sizes[0] / KD;   // 8192

    gather_wdiag_kernel<<<(KD + 255) / 256, 256>>>(W);

    const int blocks = (n_rows + ROWS_PER_BLOCK - 1) / ROWS_PER_BLOCK;
    imputation_kernel<<<blocks, THREADS>>>(h_r, b, out, n_rows);
}

// round 3
// speedup vs baseline: 3.0462x; 1.0404x over previous
#include <cuda_runtime.h>

// out[n,i] = sum_{m<K} W[i, m*D+i] * h_r[n, m*D+i] + b[i]
// N=8192, D=1024, K=8. HBM streaming: 256MB read + 32MB write -> ~36us floor.

constexpr int D = 1024;
constexpr int K = 8;
constexpr int KD = K * D;           // 8192
constexpr int THREADS = 256;        // thread t owns output cols [4t, 4t+4)
constexpr int CTAS_PER_SM = 4;
constexpr int NUM_SMS = 152;        // GB300
constexpr int GRID = CTAS_PER_SM * NUM_SMS;   // 608 persistent CTAs

// Gathered diagonal of W: g_wd[m*D + i] = W[i, m*D + i]
__device__ float g_wd[KD];

__global__ void gather_wdiag_kernel(const float* __restrict__ W) {
    const int idx = blockIdx.x * blockDim.x + threadIdx.x;
    if (idx < KD) {
        const int m = idx >> 10;
        const int i = idx & (D - 1);
        g_wd[idx] = W[(size_t)i * KD + m * D + i];
    }
}

__global__ __launch_bounds__(THREADS, CTAS_PER_SM)
void imputation_kernel(const float* __restrict__ h_r,
                       const float* __restrict__ b,
                       float* __restrict__ out,
                       int n_rows) {
    __shared__ float4 wd4[K][THREADS];

    const int t = threadIdx.x;

    // Coalesced load of the pre-gathered diagonal (8 KB, L2-resident).
    const float4* gw4 = reinterpret_cast<const float4*>(g_wd);
    #pragma unroll
    for (int m = 0; m < K; m++) {
        wd4[m][t] = gw4[m * THREADS + t];
    }
    const float4 breg = reinterpret_cast<const float4*>(b)[t];
    __syncthreads();

    // Persistent grid-stride over rows: 608 CTAs x 13-14 rows each,
    // no wave quantization (~4% imbalance vs ~14% with 2 partial waves).
    for (int n = blockIdx.x; n < n_rows; n += GRID) {
        const float4* __restrict__ hp =
            reinterpret_cast<const float4*>(h_r + (size_t)n * KD);

        // 8 independent streaming loads in flight (MLP=8 per thread).
        float4 h[K];
        #pragma unroll
        for (int m = 0; m < K; m++) {
            h[m] = __ldcs(&hp[m * (D / 4) + t]);
        }

        float4 acc = breg;
        #pragma unroll
        for (int m = 0; m < K; m++) {
            const float4 w = wd4[m][t];   // LDS.128, conflict-free
            acc.x = fmaf(h[m].x, w.x, acc.x);
            acc.y = fmaf(h[m].y, w.y, acc.y);
            acc.z = fmaf(h[m].z, w.z, acc.z);
            acc.w = fmaf(h[m].w, w.w, acc.w);
        }

        __stcs(reinterpret_cast<float4*>(out + (size_t)n * D) + t, acc);
    }
}

extern "C" void kernel_launch(void* const* d_in, const int* in_sizes, int n_in,
                              void* d_out, int out_size) {
    const float* h_r = (const float*)d_in[0];
    const float* W   = (const float*)d_in[1];
    const float* b   = (const float*)d_in[2];
    float* out       = (float*)d_out;

    const int n_rows = in_sizes[0] / KD;   // 8192

    gather_wdiag_kernel<<<(KD + 255) / 256, 256>>>(W);
    imputation_kernel<<<GRID, THREADS>>>(h_r, b, out, n_rows);
}

// round 4
// speedup vs baseline: 3.1957x; 1.0491x over previous
#include <cuda_runtime.h>

// out[n,i] = sum_{m<K} W[i, m*D+i] * h_r[n, m*D+i] + b[i]
// N=8192, D=1024, K=8. HBM streaming: 256MB read + 32MB write.
// Main kernel is at the HBM wall (~6.1 TB/s). This round: hide the
// gather-prologue launch gap with Programmatic Dependent Launch.

constexpr int D = 1024;
constexpr int K = 8;
constexpr int KD = K * D;           // 8192
constexpr int THREADS = 256;        // thread t owns output cols [4t, 4t+4)
constexpr int CTAS_PER_SM = 4;
constexpr int NUM_SMS = 152;        // GB300
constexpr int GRID = CTAS_PER_SM * NUM_SMS;   // 608 persistent CTAs

// Gathered diagonal of W: g_wd[m*D + i] = W[i, m*D + i]
__device__ float g_wd[KD];

__global__ void gather_wdiag_kernel(const float* __restrict__ W) {
    const int idx = blockIdx.x * blockDim.x + threadIdx.x;
    if (idx < KD) {
        const int m = idx >> 10;
        const int i = idx & (D - 1);
        g_wd[idx] = W[(size_t)i * KD + m * D + i];
    }
}

__global__ __launch_bounds__(THREADS, CTAS_PER_SM)
void imputation_kernel(const float* __restrict__ h_r,
                       const float* __restrict__ b,
                       float* __restrict__ out,
                       int n_rows) {
    __shared__ float4 wd4[K][THREADS];

    const int t = threadIdx.x;

    // --- PDL prologue: everything NOT depending on g_wd ---
    const float4 breg = reinterpret_cast<const float4*>(b)[t];
    const float4* __restrict__ h4 = reinterpret_cast<const float4*>(h_r);
    float4* __restrict__ o4 = reinterpret_cast<float4*>(out);

    // Wait for gather_wdiag_kernel to complete (PDL dependency).
    cudaGridDependencySynchronize();

    // Coalesced load of the pre-gathered diagonal (8 KB, L2-resident).
    const float4* gw4 = reinterpret_cast<const float4*>(g_wd);
    #pragma unroll
    for (int m = 0; m < K; m++) {
        wd4[m][t] = gw4[m * THREADS + t];
    }
    __syncthreads();

    // Persistent grid-stride over rows (608 CTAs x 13-14 rows).
    for (int n = blockIdx.x; n < n_rows; n += GRID) {
        const float4* __restrict__ hp = h4 + (size_t)n * (KD / 4);

        // 8 independent streaming loads in flight (MLP=8 per thread).
        float4 h[K];
        #pragma unroll
        for (int m = 0; m < K; m++) {
            h[m] = __ldcs(&hp[m * (D / 4) + t]);
        }

        float4 acc = breg;
        #pragma unroll
        for (int m = 0; m < K; m++) {
            const float4 w = wd4[m][t];   // LDS.128, conflict-free
            acc.x = fmaf(h[m].x, w.x, acc.x);
            acc.y = fmaf(h[m].y, w.y, acc.y);
            acc.z = fmaf(h[m].z, w.z, acc.z);
            acc.w = fmaf(h[m].w, w.w, acc.w);
        }

        __stcs(&o4[(size_t)n * (D / 4) + t], acc);
    }
}

extern "C" void kernel_launch(void* const* d_in, const int* in_sizes, int n_in,
                              void* d_out, int out_size) {
    const float* h_r = (const float*)d_in[0];
    const float* W   = (const float*)d_in[1];
    const float* b   = (const float*)d_in[2];
    float* out       = (float*)d_out;

    const int n_rows = in_sizes[0] / KD;   // 8192

    gather_wdiag_kernel<<<(KD + 255) / 256, 256>>>(W);

    // Launch main kernel with Programmatic Stream Serialization so its
    // launch + g_wd-independent prologue overlap the gather kernel.
    cudaLaunchConfig_t cfg = {};
    cfg.gridDim = dim3(GRID, 1, 1);
    cfg.blockDim = dim3(THREADS, 1, 1);
    cfg.dynamicSmemBytes = 0;
    cfg.stream = 0;
    cudaLaunchAttribute attrs[1];
    attrs[0].id = cudaLaunchAttributeProgrammaticStreamSerialization;
    attrs[0].val.programmaticStreamSerializationAllowed = 1;
    cfg.attrs = attrs;
    cfg.numAttrs = 1;
    cudaLaunchKernelEx(&cfg, imputation_kernel, h_r, b, out, n_rows);
}